// round 16
// baseline (speedup 1.0000x reference)
#include <cuda_runtime.h>
#include <cuda_bf16.h>
#include <math.h>

#define C 32
#define CM_SIZE (C * C)
#define NT 1024  // threads per block

// Scratch confusion-matrix accumulator. Invariant: zero at kernel_launch entry.
// hist_kernel accumulates; finalize_kernel reads it and resets it to zero.
__device__ float g_hist[CM_SIZE];

struct V8 { float4 a, b; };

// 256-bit streaming global load (LDG.E.256, evict-first). p must be 32B-aligned.
__device__ __forceinline__ V8 ldg256_cs(const float* p) {
    V8 r;
    asm volatile("ld.global.cs.v8.f32 {%0,%1,%2,%3,%4,%5,%6,%7}, [%8];"
        : "=f"(r.a.x), "=f"(r.a.y), "=f"(r.a.z), "=f"(r.a.w),
          "=f"(r.b.x), "=f"(r.b.y), "=f"(r.b.z), "=f"(r.b.w)
        : "l"(p));
    return r;
}

// Map float bits to unsigned such that unsigned order == float order.
__device__ __forceinline__ unsigned sortable(float f) {
    int b = __float_as_int(f);
    return (unsigned)(b ^ ((b >> 31) | 0x80000000));
}

// Lane-local argmax over 8 contiguous elements (strict > keeps first max),
// packed key = (sortable & ~31) | (31 - idx): unsigned max picks larger
// value, smaller index on (mantissa-truncated) ties.
__device__ __forceinline__ unsigned local_key8(const V8& v, int base) {
    float best = v.a.x; int bi = base;
    bool c;
    c = v.a.y > best; best = c ? v.a.y : best; bi = c ? base + 1 : bi;
    c = v.a.z > best; best = c ? v.a.z : best; bi = c ? base + 2 : bi;
    c = v.a.w > best; best = c ? v.a.w : best; bi = c ? base + 3 : bi;
    c = v.b.x > best; best = c ? v.b.x : best; bi = c ? base + 4 : bi;
    c = v.b.y > best; best = c ? v.b.y : best; bi = c ? base + 5 : bi;
    c = v.b.z > best; best = c ? v.b.z : best; bi = c ? base + 6 : bi;
    c = v.b.w > best; best = c ? v.b.w : best; bi = c ? base + 7 : bi;
    return (sortable(best) & ~31u) | (unsigned)(31 - bi);
}

// Butterfly max over the 4 lanes sharing (lane >> 2); returns argmax index.
__device__ __forceinline__ int reduce4_idx(unsigned key) {
#pragma unroll
    for (int o = 1; o < 4; o <<= 1) {
        unsigned ok = __shfl_xor_sync(0xffffffffu, key, o);
        key = key > ok ? key : ok;
    }
    return 31 - (int)(key & 31u);
}

__global__ void __launch_bounds__(NT, 2) hist_kernel(
    const float* __restrict__ yt,
    const float* __restrict__ yp,
    int n_rows)
{
    __shared__ int sh[CM_SIZE];
    for (int i = threadIdx.x; i < CM_SIZE; i += NT) sh[i] = 0;
    __syncthreads();

    const int lane = threadIdx.x & 31;
    const int gw   = (blockIdx.x * NT + threadIdx.x) >> 5;    // global warp id
    const int nw   = (gridDim.x * NT) >> 5;                   // total warps
    const int base = (lane & 3) * 8;       // element offset within a row
    const bool is_head = (lane & 3) == 0;  // lanes 0,4,...,28: one per row

    // 8 rows per warp-iteration, ONE LDG.256 per tensor (1024B each, fully
    // coalesced): lane covers 8 contiguous elements of row (lane >> 2).
    const int ngroups = n_rows >> 3;
    for (int g = gw; g < ngroups; g += nw) {
        const float* at = yt + (size_t)g * 8 * C;
        const float* ap = yp + (size_t)g * 8 * C;
        V8 t = ldg256_cs(at + lane * 8);
        V8 p = ldg256_cs(ap + lane * 8);

        int ti = reduce4_idx(local_key8(t, base));
        int pi = reduce4_idx(local_key8(p, base));

        if (is_head)
            atomicAdd(&sh[ti * C + pi], 1);
    }

    // Tail (n_rows % 8 rows): scalar, handled by global warp 0.
    if (gw == 0) {
        int tail = n_rows & 7;
        if (lane < tail) {
            size_t r = (size_t)(n_rows & ~7) + lane;
            const float* a = yt + r * C;
            const float* b = yp + r * C;
            float bt = a[0]; int ti = 0;
            float bp = b[0]; int pi = 0;
#pragma unroll
            for (int k = 1; k < C; k++) {
                if (a[k] > bt) { bt = a[k]; ti = k; }
                if (b[k] > bp) { bp = b[k]; pi = k; }
            }
            atomicAdd(&sh[ti * C + pi], 1);
        }
    }

    __syncthreads();
    // Staggered flush: block b starts at a different histogram offset so
    // concurrent blocks hit different addresses / LTS slices instead of
    // convoying per-address at the L2 atomic ALU.
    {
        int off = (blockIdx.x * 131) & (CM_SIZE - 1);
        for (int i = threadIdx.x; i < CM_SIZE; i += NT) {
            int idx = (i + off) & (CM_SIZE - 1);
            int v = sh[idx];
            if (v) atomicAdd(&g_hist[idx], (float)v);
        }
    }
}

__global__ void finalize_kernel(const float* __restrict__ cm_in, float* __restrict__ out) {
    int j = threadIdx.x;  // column index, single warp
    float colsum = 0.0f;
    float tp = 0.0f;
#pragma unroll
    for (int i = 0; i < C; i++) {
        float v = g_hist[i * C + j] + cm_in[i * C + j];
        colsum += v;
        if (i == j) tp = v;
    }
    const float EPS = 1.1920928955078125e-07f;  // FLT_EPSILON
    float prec = tp / (colsum + EPS);
#pragma unroll
    for (int o = 16; o > 0; o >>= 1)
        prec += __shfl_xor_sync(0xffffffffu, prec, o);
    if (j == 0) out[0] = prec * (1.0f / C);
    __syncwarp();
    // Reset scratch for the next graph replay. Safe: every lane's loads were
    // consumed by the shfl reduction above, which precedes these stores in
    // warp-synchronous program order.
#pragma unroll
    for (int k = 0; k < C; k++) g_hist[j * C + k] = 0.0f;
}

extern "C" void kernel_launch(void* const* d_in, const int* in_sizes, int n_in,
                              void* d_out, int out_size) {
    const float* y_true = (const float*)d_in[0];
    const float* y_pred = (const float*)d_in[1];
    const float* cm_in  = (const float*)d_in[2];
    float* out = (float*)d_out;

    int n_rows = in_sizes[0] / C;

    // 152 SMs * 2 blocks of 1024 threads: minimal block count (minimal
    // end-of-kernel atomic drain) at full 2048 threads/SM occupancy.
    hist_kernel<<<152 * 2, NT>>>(y_true, y_pred, n_rows);
    finalize_kernel<<<1, C>>>(cm_in, out);
}